// round 2
// baseline (speedup 1.0000x reference)
#include <cuda_runtime.h>
#include <cstdint>

// Problem constants (fixed by the dataset)
#define B_SZ    16
#define IN_F    8192
#define OUT_F   8192
#define GRP     128
#define NGRP    (IN_F / GRP)      // 64
#define CHUNK   2048
#define NCHUNK  (IN_F / CHUNK)    // 4
#define GPC     (CHUNK / GRP)     // 16 groups per chunk
#define XPAD    20                // 80B column stride: conflict-free LDS.128, 16B aligned
#define THREADS 256
#define WARPS   8
#define R       4                 // rows per warp  -> crossbar/fma balanced
#define RPB     (WARPS * R)       // 32 rows per block
#define SMEM_X      (CHUNK * XPAD)        // floats
#define SMEM_SC     (RPB * NGRP)          // 2048 floats (block scales)
#define SMEM_BYTES  ((SMEM_X + SMEM_SC) * 4)   // 172032 B

typedef unsigned long long ull;

__device__ __forceinline__ ull pack2(float v) {
    ull r; asm("mov.b64 %0, {%1, %1};" : "=l"(r) : "f"(v)); return r;
}
__device__ __forceinline__ void fma2(ull& d, ull a, ull b) {
    asm("fma.rn.f32x2 %0, %1, %2, %0;" : "+l"(d) : "l"(a), "l"(b));
}
__device__ __forceinline__ ull add2(ull a, ull b) {
    ull r; asm("add.rn.f32x2 %0, %1, %2;" : "=l"(r) : "l"(a), "l"(b)); return r;
}
__device__ __forceinline__ void unpack2(ull v, float& lo, float& hi) {
    asm("mov.b64 {%0, %1}, %2;" : "=f"(lo), "=f"(hi) : "l"(v));
}

__global__ void __launch_bounds__(THREADS, 1)
axcore_linear_kernel(const float* __restrict__ x,
                     const float* __restrict__ W,
                     const float* __restrict__ scale,
                     const float* __restrict__ bias,
                     float* __restrict__ out)
{
    extern __shared__ float smem[];
    float* xs = smem;                 // [CHUNK][XPAD]  x transposed
    float* sc = smem + SMEM_X;        // [RPB][NGRP]    block scales

    const int tid  = threadIdx.x;
    const int lane = tid & 31;
    const int warp = tid >> 5;
    const int blk_row0 = blockIdx.x * RPB;
    const int row0 = blk_row0 + warp * R;

    // ---- cache this block's scales in smem (coalesced)
    for (int idx = tid; idx < RPB * NGRP; idx += THREADS)
        sc[idx] = scale[(size_t)(blk_row0 + (idx >> 6)) * NGRP + (idx & 63)];

    // acc[r][bp] : f32x2 over batch pair (2bp, 2bp+1)
    ull acc[R][8];
#pragma unroll
    for (int r = 0; r < R; r++)
#pragma unroll
        for (int bp = 0; bp < 8; bp++) acc[r][bp] = 0ull;

    // row base pointers (hoisted 64-bit math)
    const float* wrow[R];
#pragma unroll
    for (int r = 0; r < R; r++) wrow[r] = W + (size_t)(row0 + r) * IN_F;

    float wA[R][4], wB[R][4];
    float sA[R], sB[R];

    for (int ci = 0; ci < NCHUNK; ci++) {
        const int cbase = ci * CHUNK;

        // ---- stage x chunk transposed: warp covers 4 batches x 8 cols
        //      LDG: 4 fully-used 32B sectors / warp.  STS: banks 20c+bl -> all 32, conflict-free.
        for (int idx = tid; idx < CHUNK * B_SZ; idx += THREADS) {
            const int c  = idx & 7;
            const int bl = (idx >> 3) & 3;
            const int j  = ((idx >> 5) & (CHUNK / 8 - 1)) * 8 + c;
            const int b  = (idx >> 13) * 4 + bl;
            xs[j * XPAD + b] = x[(size_t)b * IN_F + cbase + j];
        }
        __syncthreads();

#define PREFETCH(buf, sbuf, g) do {                                           \
        const int _c = cbase + (g) * GRP + lane;                              \
        _Pragma("unroll")                                                     \
        for (int r = 0; r < R; r++) {                                         \
            const float* _rp = wrow[r] + _c;                                  \
            _Pragma("unroll")                                                 \
            for (int k = 0; k < 4; k++) buf[r][k] = __ldg(_rp + 32 * k);      \
            sbuf[r] = sc[(warp * R + r) * NGRP + ci * GPC + (g)];             \
        } } while (0)

#define COMPUTE(buf, sbuf, g) do {                                            \
        _Pragma("unroll")                                                     \
        for (int k = 0; k < 4; k++) {                                         \
            const float* _xp = xs + ((g) * GRP + lane + 32 * k) * XPAD;       \
            ull x2[8];                                                        \
            _Pragma("unroll")                                                 \
            for (int q = 0; q < 4; q++) {                                     \
                ulonglong2 _v = *reinterpret_cast<const ulonglong2*>(_xp + 4 * q); \
                x2[2 * q] = _v.x; x2[2 * q + 1] = _v.y;                       \
            }                                                                 \
            _Pragma("unroll")                                                 \
            for (int r = 0; r < R; r++) {                                     \
                const ull _w2 = pack2(buf[r][k] * sbuf[r]);                   \
                _Pragma("unroll")                                             \
                for (int bp = 0; bp < 8; bp++) fma2(acc[r][bp], _w2, x2[bp]); \
            }                                                                 \
        } } while (0)

        PREFETCH(wA, sA, 0);
        for (int g = 0; g < GPC; g += 2) {
            PREFETCH(wB, sB, g + 1);
            COMPUTE(wA, sA, g);
            if (g + 2 < GPC) PREFETCH(wA, sA, g + 2);
            COMPUTE(wB, sB, g + 1);
        }
        __syncthreads();
    }

    // ---- butterfly reduction across lanes (one-time, ~µs)
#pragma unroll
    for (int r = 0; r < R; r++)
#pragma unroll
        for (int bp = 0; bp < 8; bp++) {
            ull v = acc[r][bp];
#pragma unroll
            for (int off = 16; off > 0; off >>= 1)
                v = add2(v, __shfl_xor_sync(0xffffffffu, v, off));
            acc[r][bp] = v;
        }

    // ---- writeback: lane (r*8+bp) owns (row0+r, batches 2bp,2bp+1)
#pragma unroll
    for (int r = 0; r < R; r++)
#pragma unroll
        for (int bp = 0; bp < 8; bp++)
            if (lane == r * 8 + bp) {
                const int row = row0 + r;
                const float bv = __ldg(bias + row);
                float lo, hi;
                unpack2(acc[r][bp], lo, hi);
                out[(size_t)(2 * bp)     * OUT_F + row] = lo + bv;
                out[(size_t)(2 * bp + 1) * OUT_F + row] = hi + bv;
            }
}

extern "C" void kernel_launch(void* const* d_in, const int* in_sizes, int n_in,
                              void* d_out, int out_size)
{
    const float* x     = (const float*)d_in[0]; // [16, 8192]
    const float* W     = (const float*)d_in[1]; // [8192, 8192]
    const float* scale = (const float*)d_in[2]; // [8192, 64]
    const float* bias  = (const float*)d_in[3]; // [1, 8192]
    // d_in[4] = types — constant lookup in reference; no float math: unused
    float* out = (float*)d_out;                 // [16, 8192]

    cudaFuncSetAttribute(axcore_linear_kernel,
                         cudaFuncAttributeMaxDynamicSharedMemorySize, SMEM_BYTES);

    dim3 grid(OUT_F / RPB); // 256
    dim3 block(THREADS);    // 256
    axcore_linear_kernel<<<grid, block, SMEM_BYTES>>>(x, W, scale, bias, out);
}

// round 3
// speedup vs baseline: 1.5596x; 1.5596x over previous
#include <cuda_runtime.h>
#include <cstdint>

// Problem constants (fixed by the dataset)
#define B_SZ    16
#define IN_F    8192
#define OUT_F   8192
#define GRP     128
#define NGRP    64            // scale groups along in-features
#define CHUNK   1024          // x columns staged per phase
#define GPC     8             // groups per chunk
#define XPAD    20            // 80B column stride -> conflict-free LDS.128
#define THREADS 256
#define WARPS   8
#define R       8             // rows per warp
#define RPB     64            // rows per block
#define NSTAGE  4             // W pipeline stages

#define XS_FLOATS   (CHUNK * XPAD)       // 20480
#define WS_FLOATS   (RPB * GRP)          // 8192 per stage
#define SC_FLOATS   (RPB * NGRP)         // 4096
#define SMEM_BYTES  ((XS_FLOATS + NSTAGE * WS_FLOATS + SC_FLOATS) * 4) // 229376

typedef unsigned long long ull;

__device__ __forceinline__ ull pack2(float v) {
    ull r; asm("mov.b64 %0, {%1, %1};" : "=l"(r) : "f"(v)); return r;
}
__device__ __forceinline__ void fma2(ull& d, ull a, ull b) {
    asm("fma.rn.f32x2 %0, %1, %2, %0;" : "+l"(d) : "l"(a), "l"(b));
}
__device__ __forceinline__ ull add2(ull a, ull b) {
    ull r; asm("add.rn.f32x2 %0, %1, %2;" : "=l"(r) : "l"(a), "l"(b)); return r;
}
__device__ __forceinline__ void unpack2(ull v, float& lo, float& hi) {
    asm("mov.b64 {%0, %1}, %2;" : "=f"(lo), "=f"(hi) : "l"(v));
}
__device__ __forceinline__ void cp_async16(uint32_t dst, const float* src) {
    asm volatile("cp.async.cg.shared.global [%0], [%1], 16;" :: "r"(dst), "l"(src));
}
__device__ __forceinline__ void cp_commit() {
    asm volatile("cp.async.commit_group;");
}
__device__ __forceinline__ void cp_wait2() {
    asm volatile("cp.async.wait_group 2;");
}

__global__ void __launch_bounds__(THREADS, 1)
axcore_linear_kernel(const float* __restrict__ x,
                     const float* __restrict__ W,
                     const float* __restrict__ scale,
                     const float* __restrict__ bias,
                     float* __restrict__ out)
{
    extern __shared__ float smem[];
    float* xs = smem;                              // [CHUNK][XPAD] x transposed
    float* ws = smem + XS_FLOATS;                  // 4 stages of [RPB][GRP]
    float* sc = smem + XS_FLOATS + NSTAGE * WS_FLOATS; // [RPB][NGRP]

    const int tid  = threadIdx.x;
    const int lane = tid & 31;
    const int warp = tid >> 5;
    const int row0 = blockIdx.x * RPB;
    const float* Wb = W + (size_t)row0 * IN_F;
    const uint32_t ws_u32 = (uint32_t)__cvta_generic_to_shared(ws);

    // ---- W stage issue: 8 cp.async(16B) per thread covers [64 rows][128 cols]
#define ISSUE_W(gn) do {                                                      \
        if ((gn) < NGRP) {                                                    \
            const float* _src = Wb + (size_t)(gn) * GRP;                      \
            const uint32_t _db = ws_u32 + ((gn) & 3) * (WS_FLOATS * 4);       \
            _Pragma("unroll")                                                 \
            for (int j = 0; j < 8; j++) {                                     \
                const int i = tid + THREADS * j;  /* 0..2047 */               \
                const int r = i >> 5, cf = i & 31;                            \
                cp_async16(_db + (uint32_t)(r * GRP + cf * 4) * 4,            \
                           _src + (size_t)r * IN_F + cf * 4);                 \
            }                                                                 \
        }                                                                     \
        cp_commit();                                                          \
    } while (0)

    // ---- x chunk staging: LDG 32B sectors fully used, STS conflict-free
#define STAGE_X(ci) do {                                                      \
        const int _cb = (ci) * CHUNK;                                         \
        for (int idx = tid; idx < CHUNK * B_SZ; idx += THREADS) {             \
            const int c  = idx & 7;                                           \
            const int bl = (idx >> 3) & 3;                                    \
            const int j  = ((idx >> 5) & (CHUNK / 8 - 1)) * 8 + c;            \
            const int b  = ((idx >> 12) << 2) + bl;                           \
            xs[j * XPAD + b] = x[(size_t)b * IN_F + _cb + j];                 \
        }                                                                     \
    } while (0)

    // ---- prologue: fill 3 W stages, stage scales + x chunk 0
    ISSUE_W(0); ISSUE_W(1); ISSUE_W(2);
    for (int idx = tid; idx < SC_FLOATS; idx += THREADS)
        sc[idx] = scale[(size_t)row0 * NGRP + idx];   // [r][g] contiguous
    STAGE_X(0);

    ull acc[R][8];
#pragma unroll
    for (int r = 0; r < R; r++)
#pragma unroll
        for (int bp = 0; bp < 8; bp++) acc[r][bp] = 0ull;

    // ---- main loop over 64 scale groups
    for (int g = 0; g < NGRP; g++) {
        cp_wait2();             // group g landed
        __syncthreads();        // visible to all; all done with group g-1
        ISSUE_W(g + 3);         // into slot (g-1)&3, consumed last iter
        if (g && (g & (GPC - 1)) == 0) {   // chunk boundary
            STAGE_X(g >> 3);
            __syncthreads();
        }

        const float* wsl = ws + (g & 3) * WS_FLOATS + (warp * R) * GRP;
        float s[R];
#pragma unroll
        for (int r = 0; r < R; r++) s[r] = sc[(warp * R + r) * NGRP + g];

        const int jb = (g & (GPC - 1)) * GRP;
#pragma unroll
        for (int k = 0; k < 4; k++) {
            const float* xp = xs + (jb + lane + 32 * k) * XPAD;
            ull x2[8];
#pragma unroll
            for (int q = 0; q < 4; q++) {
                ulonglong2 v = *reinterpret_cast<const ulonglong2*>(xp + 4 * q);
                x2[2 * q] = v.x; x2[2 * q + 1] = v.y;
            }
            float w[R];
#pragma unroll
            for (int r = 0; r < R; r++) w[r] = wsl[r * GRP + lane + 32 * k];
#pragma unroll
            for (int r = 0; r < R; r++) {
                const ull w2 = pack2(w[r] * s[r]);
#pragma unroll
                for (int bp = 0; bp < 8; bp++) fma2(acc[r][bp], w2, x2[bp]);
            }
        }
    }

    // ---- butterfly reduction across lanes (one-time)
#pragma unroll
    for (int r = 0; r < R; r++)
#pragma unroll
        for (int bp = 0; bp < 8; bp++) {
            ull v = acc[r][bp];
#pragma unroll
            for (int off = 16; off > 0; off >>= 1)
                v = add2(v, __shfl_xor_sync(0xffffffffu, v, off));
            acc[r][bp] = v;
        }

    // ---- writeback: (r,bp) index 0..63 -> lanes {idx, idx-32}, 2 stores/lane
#pragma unroll
    for (int r = 0; r < R; r++)
#pragma unroll
        for (int bp = 0; bp < 8; bp++) {
            const int idx = r * 8 + bp;
            if ((idx & 31) == lane) {
                const int row = row0 + warp * R + r;
                const float bv = __ldg(bias + row);
                float lo, hi;
                unpack2(acc[r][bp], lo, hi);
                out[(size_t)(2 * bp)     * OUT_F + row] = lo + bv;
                out[(size_t)(2 * bp + 1) * OUT_F + row] = hi + bv;
            }
        }
}

extern "C" void kernel_launch(void* const* d_in, const int* in_sizes, int n_in,
                              void* d_out, int out_size)
{
    const float* x     = (const float*)d_in[0]; // [16, 8192]
    const float* W     = (const float*)d_in[1]; // [8192, 8192]
    const float* scale = (const float*)d_in[2]; // [8192, 64]
    const float* bias  = (const float*)d_in[3]; // [1, 8192]
    // d_in[4] = types — constant lookup in reference; no float math: unused
    float* out = (float*)d_out;                 // [16, 8192]

    cudaFuncSetAttribute(axcore_linear_kernel,
                         cudaFuncAttributeMaxDynamicSharedMemorySize, SMEM_BYTES);

    dim3 grid(OUT_F / RPB); // 128
    dim3 block(THREADS);    // 256
    axcore_linear_kernel<<<grid, block, SMEM_BYTES>>>(x, W, scale, bias, out);
}

// round 5
// speedup vs baseline: 2.0268x; 1.2996x over previous
#include <cuda_runtime.h>
#include <cstdint>

#define B_SZ    16
#define IN_F    8192
#define OUT_F   8192
#define GRP     128
#define NGRP    64
#define CHUNK   1024           // x columns staged per phase
#define GPC     8              // groups per chunk
#define XPAD    20             // 80B col stride -> conflict-free LDS.128
#define THREADS 512
#define RPB     64             // rows per block
#define NSTAGE  4

// smem byte layout
#define MBAR_OFF   0                                   // 8 barriers x 8B
#define WS_OFF     128
#define WS_STAGE   (RPB * GRP * 4)                     // 32768 B
#define XS_OFF     (WS_OFF + NSTAGE * WS_STAGE)        // 131200
#define XS_BYTES   (CHUNK * XPAD * 4)                  // 81920
#define SC_OFF     (XS_OFF + XS_BYTES)                 // 213120
#define SC_BYTES   (RPB * NGRP * 4)                    // 16384
#define SMEM_TOTAL (SC_OFF + SC_BYTES)                 // 229504

typedef unsigned long long ull;

__device__ __forceinline__ ull pack2(float v) {
    ull r; asm("mov.b64 %0, {%1, %1};" : "=l"(r) : "f"(v)); return r;
}
__device__ __forceinline__ void fma2(ull& d, ull a, ull b) {
    asm("fma.rn.f32x2 %0, %1, %2, %0;" : "+l"(d) : "l"(a), "l"(b));
}
__device__ __forceinline__ ull add2(ull a, ull b) {
    ull r; asm("add.rn.f32x2 %0, %1, %2;" : "=l"(r) : "l"(a), "l"(b)); return r;
}
__device__ __forceinline__ void unpack2(ull v, float& lo, float& hi) {
    asm("mov.b64 {%0, %1}, %2;" : "=f"(lo), "=f"(hi) : "l"(v));
}
__device__ __forceinline__ void cp_async16(uint32_t dst, const float* src) {
    asm volatile("cp.async.cg.shared.global [%0], [%1], 16;" :: "r"(dst), "l"(src));
}
__device__ __forceinline__ void mbar_init(uint32_t a, uint32_t cnt) {
    asm volatile("mbarrier.init.shared.b64 [%0], %1;" :: "r"(a), "r"(cnt) : "memory");
}
__device__ __forceinline__ void mbar_arrive(uint32_t a) {
    asm volatile("mbarrier.arrive.shared.b64 _, [%0];" :: "r"(a) : "memory");
}
// .noinc: this thread's async-completion COUNTS against the initialized
// expected-arrival count (plain form is self-balancing => deadlock).
__device__ __forceinline__ void cpasync_mbar_arrive_noinc(uint32_t a) {
    asm volatile("cp.async.mbarrier.arrive.noinc.shared::cta.b64 [%0];" :: "r"(a) : "memory");
}
__device__ __forceinline__ void mbar_wait(uint32_t a, uint32_t parity) {
    asm volatile(
        "{\n\t.reg .pred P;\n\t"
        "WL_%=:\n\t"
        "mbarrier.try_wait.parity.acquire.cta.shared::cta.b64 P, [%0], %1, 0x989680;\n\t"
        "@P bra.uni WD_%=;\n\t"
        "bra.uni WL_%=;\n\t"
        "WD_%=:\n\t}"
        :: "r"(a), "r"(parity) : "memory");
}

__global__ void __launch_bounds__(THREADS, 1)
axcore_linear_kernel(const float* __restrict__ x,
                     const float* __restrict__ W,
                     const float* __restrict__ scale,
                     const float* __restrict__ bias,
                     float* __restrict__ out)
{
    extern __shared__ char smem[];
    float* ws = reinterpret_cast<float*>(smem + WS_OFF);
    float* xs = reinterpret_cast<float*>(smem + XS_OFF);
    float* sc = reinterpret_cast<float*>(smem + SC_OFF);
    const uint32_t smem_u32 = (uint32_t)__cvta_generic_to_shared(smem);
    const uint32_t ws_u32   = smem_u32 + WS_OFF;
#define FULL_BAR(s)  (smem_u32 + MBAR_OFF + (s) * 8)
#define EMPTY_BAR(s) (smem_u32 + MBAR_OFF + 32 + (s) * 8)

    const int tid  = threadIdx.x;
    const int lane = tid & 31;
    const int warp = tid >> 5;
    const int half = warp >> 3;          // batch half (0: b0-7, 1: b8-15)
    const int wr0  = (warp & 7) * 8;     // warp's first row within block
    const int row0 = blockIdx.x * RPB;
    const float* Wb = W + (size_t)row0 * IN_F;

    // ---- barrier init
    if (tid == 0) {
#pragma unroll
        for (int s = 0; s < NSTAGE; s++) {
            mbar_init(FULL_BAR(s), THREADS);   // 512 noinc async arrivals
            mbar_init(EMPTY_BAR(s), THREADS);  // 512 thread arrivals
        }
    }
    __syncthreads();

    // ---- issue W group gi into slot gi&3 (all threads; 4x cp.async16 each)
#define ISSUE_W(gi) do {                                                      \
        const int _s = (gi) & 3;                                              \
        mbar_wait(EMPTY_BAR(_s), (((gi) >> 2) & 1) ^ 1);                      \
        const float* _src = Wb + (size_t)(gi) * GRP;                          \
        const uint32_t _db = ws_u32 + _s * WS_STAGE;                          \
        _Pragma("unroll")                                                     \
        for (int j = 0; j < 4; j++) {                                         \
            const int i = tid + THREADS * j;  /* 0..2047: (row, 16B chunk) */ \
            const int r = i >> 5, cf = i & 31;                                \
            cp_async16(_db + (uint32_t)(r * GRP + cf * 4) * 4,                \
                       _src + (size_t)r * IN_F + cf * 4);                     \
        }                                                                     \
        cpasync_mbar_arrive_noinc(FULL_BAR(_s));                              \
    } while (0)

    // ---- x chunk staging (transposed, conflict-free STS; validated mapping)
#define STAGE_X(ci) do {                                                      \
        const int _cb = (ci) * CHUNK;                                         \
        for (int idx = tid; idx < CHUNK * B_SZ; idx += THREADS) {             \
            const int c  = idx & 7;                                           \
            const int bl = (idx >> 3) & 3;                                    \
            const int j  = ((idx >> 5) & (CHUNK / 8 - 1)) * 8 + c;            \
            const int b  = ((idx >> 12) << 2) + bl;                           \
            xs[j * XPAD + b] = x[(size_t)b * IN_F + _cb + j];                 \
        }                                                                     \
    } while (0)

    // ---- prologue: fill 3 W stages; stage scales + x chunk 0
    ISSUE_W(0); ISSUE_W(1); ISSUE_W(2);
    for (int idx = tid; idx < RPB * NGRP; idx += THREADS)
        sc[idx] = scale[(size_t)row0 * NGRP + idx];
    STAGE_X(0);
    __syncthreads();

    // acc[r][q]: f32x2 over batches (half*8 + 2q, half*8 + 2q + 1)
    ull acc[8][4];
#pragma unroll
    for (int r = 0; r < 8; r++)
#pragma unroll
        for (int q = 0; q < 4; q++) acc[r][q] = 0ull;

    // ---- main loop over 64 groups, mbarrier-paced (no block barrier)
    for (int g = 0; g < NGRP; g++) {
        if (g + 3 < NGRP) ISSUE_W(g + 3);
        mbar_wait(FULL_BAR(g & 3), (g >> 2) & 1);

        if (g && (g & (GPC - 1)) == 0) {   // chunk boundary: restage x
            __syncthreads();
            STAGE_X(g >> 3);
            __syncthreads();
        }

        const float* wst = ws + (g & 3) * (RPB * GRP) + wr0 * GRP;
        const float* xph = xs + half * 8;
        float s[8];
#pragma unroll
        for (int r = 0; r < 8; r++) s[r] = sc[(wr0 + r) * NGRP + g];

        const int jb = (g & (GPC - 1)) * GRP;
#pragma unroll
        for (int k = 0; k < 4; k++) {
            const float* xp = xph + (jb + lane + 32 * k) * XPAD;
            ull x2[4];
            {
                ulonglong2 v0 = *reinterpret_cast<const ulonglong2*>(xp);
                ulonglong2 v1 = *reinterpret_cast<const ulonglong2*>(xp + 4);
                x2[0] = v0.x; x2[1] = v0.y; x2[2] = v1.x; x2[3] = v1.y;
            }
#pragma unroll
            for (int r = 0; r < 8; r++) {
                const float wv = wst[r * GRP + lane + 32 * k];
                const ull w2 = pack2(wv * s[r]);
#pragma unroll
                for (int q = 0; q < 4; q++) fma2(acc[r][q], w2, x2[q]);
            }
        }
        mbar_arrive(EMPTY_BAR(g & 3));
    }

    // ---- butterfly reduction across lanes
#pragma unroll
    for (int r = 0; r < 8; r++)
#pragma unroll
        for (int q = 0; q < 4; q++) {
            ull v = acc[r][q];
#pragma unroll
            for (int off = 16; off > 0; off >>= 1)
                v = add2(v, __shfl_xor_sync(0xffffffffu, v, off));
            acc[r][q] = v;
        }

    // ---- writeback: lane (r*4+q) stores batches (half*8+2q, +1) of row wr0+r
#pragma unroll
    for (int r = 0; r < 8; r++)
#pragma unroll
        for (int q = 0; q < 4; q++)
            if (lane == r * 4 + q) {
                const int row = row0 + wr0 + r;
                const int b0  = half * 8 + 2 * q;
                const float bv = __ldg(bias + row);
                float lo, hi;
                unpack2(acc[r][q], lo, hi);
                out[(size_t)b0 * OUT_F + row]       = lo + bv;
                out[(size_t)(b0 + 1) * OUT_F + row] = hi + bv;
            }
}

extern "C" void kernel_launch(void* const* d_in, const int* in_sizes, int n_in,
                              void* d_out, int out_size)
{
    const float* x     = (const float*)d_in[0]; // [16, 8192]
    const float* W     = (const float*)d_in[1]; // [8192, 8192]
    const float* scale = (const float*)d_in[2]; // [8192, 64]
    const float* bias  = (const float*)d_in[3]; // [1, 8192]
    // d_in[4] = types — constant lookup in reference; no float math: unused
    float* out = (float*)d_out;                 // [16, 8192]

    cudaFuncSetAttribute(axcore_linear_kernel,
                         cudaFuncAttributeMaxDynamicSharedMemorySize, SMEM_TOTAL);

    dim3 grid(OUT_F / RPB); // 128
    dim3 block(THREADS);    // 512
    axcore_linear_kernel<<<grid, block, SMEM_TOTAL>>>(x, W, scale, bias, out);
}

// round 7
// speedup vs baseline: 2.5091x; 1.2380x over previous
#include <cuda_runtime.h>
#include <cstdint>

#define B_SZ    16
#define IN_F    8192
#define OUT_F   8192
#define GRP     128
#define NGRP    64
#define CHUNK   512            // x columns per chunk
#define GPC     4              // groups per x chunk
#define NCHUNK  16
#define THREADS 512
#define RPB     64             // rows per block
#define WST     3              // W ring stages
#define XST     3              // x ring stages

#define WS_STAGE_F  (RPB * GRP)        // 8192 floats / stage
#define XR_STAGE_F  (B_SZ * CHUNK)     // 8192 floats / stage
#define WS_OFF      128
#define XR_OFF      (WS_OFF + WST * WS_STAGE_F * 4)   // 98432
#define SC_OFF      (XR_OFF + XST * XR_STAGE_F * 4)   // 196736
#define SMEM_TOTAL  (SC_OFF + RPB * NGRP * 4)         // 213120

typedef unsigned long long ull;

__device__ __forceinline__ ull pack2(float v) {
    ull r; asm("mov.b64 %0, {%1, %1};" : "=l"(r) : "f"(v)); return r;
}
__device__ __forceinline__ ull packab(float a, float b) {
    ull r; asm("mov.b64 %0, {%1, %2};" : "=l"(r) : "f"(a), "f"(b)); return r;
}
__device__ __forceinline__ void fma2(ull& d, ull a, ull b) {
    asm("fma.rn.f32x2 %0, %1, %2, %0;" : "+l"(d) : "l"(a), "l"(b));
}
__device__ __forceinline__ ull add2(ull a, ull b) {
    ull r; asm("add.rn.f32x2 %0, %1, %2;" : "=l"(r) : "l"(a), "l"(b)); return r;
}
__device__ __forceinline__ void unpack2(ull v, float& lo, float& hi) {
    asm("mov.b64 {%0, %1}, %2;" : "=f"(lo), "=f"(hi) : "l"(v));
}
__device__ __forceinline__ void cp_async16(uint32_t dst, const float* src) {
    asm volatile("cp.async.cg.shared.global [%0], [%1], 16;" :: "r"(dst), "l"(src));
}
__device__ __forceinline__ void mbar_init(uint32_t a, uint32_t cnt) {
    asm volatile("mbarrier.init.shared.b64 [%0], %1;" :: "r"(a), "r"(cnt) : "memory");
}
__device__ __forceinline__ void mbar_arrive(uint32_t a) {
    asm volatile("mbarrier.arrive.shared.b64 _, [%0];" :: "r"(a) : "memory");
}
__device__ __forceinline__ void cpasync_mbar_arrive_noinc(uint32_t a) {
    asm volatile("cp.async.mbarrier.arrive.noinc.shared::cta.b64 [%0];" :: "r"(a) : "memory");
}
__device__ __forceinline__ void mbar_wait(uint32_t a, uint32_t parity) {
    asm volatile(
        "{\n\t.reg .pred P;\n\t"
        "WL_%=:\n\t"
        "mbarrier.try_wait.parity.acquire.cta.shared::cta.b64 P, [%0], %1, 0x989680;\n\t"
        "@P bra.uni WD_%=;\n\t"
        "bra.uni WL_%=;\n\t"
        "WD_%=:\n\t}"
        :: "r"(a), "r"(parity) : "memory");
}

__global__ void __launch_bounds__(THREADS, 1)
axcore_linear_kernel(const float* __restrict__ x,
                     const float* __restrict__ W,
                     const float* __restrict__ scale,
                     const float* __restrict__ bias,
                     float* __restrict__ out)
{
    extern __shared__ char smem[];
    float* ws = reinterpret_cast<float*>(smem + WS_OFF);
    float* xr = reinterpret_cast<float*>(smem + XR_OFF);
    float* sc = reinterpret_cast<float*>(smem + SC_OFF);
    const uint32_t smem_u32 = (uint32_t)__cvta_generic_to_shared(smem);
#define FULLW(s)  (smem_u32 + (s) * 8)
#define EMPTYW(s) (smem_u32 + 24 + (s) * 8)
#define FULLX(s)  (smem_u32 + 48 + (s) * 8)

    const int tid  = threadIdx.x;
    const int lane = tid & 31;
    const int warp = tid >> 5;
    const int half = warp >> 3;          // batch half
    const int wr0  = (warp & 7) * 8;     // first row of warp's tile
    const int row0 = blockIdx.x * RPB;
    const float* Wb = W + (size_t)row0 * IN_F;
    const bool prod = (warp < 4);        // producer warps (tid < 128)

    if (tid == 0) {
#pragma unroll
        for (int s = 0; s < 3; s++) {
            mbar_init(FULLW(s), 128);    // noinc arrivals from 128 producer threads
            mbar_init(EMPTYW(s), 16);    // one elected arrive per warp
            mbar_init(FULLX(s), 128);
        }
    }
    __syncthreads();

    // ---- W group gi -> slot: producer threads, 16 x cp.async16 each
#define ISSUE_W(gi, slot) do {                                                \
        const float* _src = Wb + (size_t)(gi) * GRP;                          \
        const uint32_t _db = smem_u32 + WS_OFF + (slot) * (WS_STAGE_F * 4);   \
        _Pragma("unroll")                                                     \
        for (int j = 0; j < 16; j++) {                                        \
            const int i = tid + 128 * j;        /* 0..2047 */                 \
            const int r = i >> 5, cf = i & 31;  /* 64 rows x 32 x 16B */      \
            cp_async16(_db + (uint32_t)(r * GRP + cf * 4) * 4,                \
                       _src + (size_t)r * IN_F + cf * 4);                     \
        }                                                                     \
        cpasync_mbar_arrive_noinc(FULLW(slot));                               \
    } while (0)

    // ---- x chunk c -> slot: [16 batches][512 cols] untransposed
#define ISSUE_X(c, slot) do {                                                 \
        const float* _sx = x + (size_t)(c) * CHUNK;                           \
        const uint32_t _db = smem_u32 + XR_OFF + (slot) * (XR_STAGE_F * 4);   \
        _Pragma("unroll")                                                     \
        for (int j = 0; j < 16; j++) {                                        \
            const int i = tid + 128 * j;          /* 0..2047 */               \
            const int b = i >> 7, cf = i & 127;   /* 16 rows x 128 x 16B */   \
            cp_async16(_db + (uint32_t)(b * CHUNK + cf * 4) * 4,              \
                       _sx + (size_t)b * IN_F + cf * 4);                      \
        }                                                                     \
        cpasync_mbar_arrive_noinc(FULLX(slot));                               \
    } while (0)

    // ---- prologue: x chunk 0, W groups 0 & 1; stage scales
    if (prod) { ISSUE_X(0, 0); ISSUE_W(0, 0); ISSUE_W(1, 1); }
    for (int idx = tid; idx < RPB * NGRP; idx += THREADS)
        sc[idx] = scale[(size_t)row0 * NGRP + idx];
    __syncthreads();   // sc visible before use

    ull acc[8][4];
#pragma unroll
    for (int r = 0; r < 8; r++)
#pragma unroll
        for (int q = 0; q < 4; q++) acc[r][q] = 0ull;

    // cursors
    int cwsl = 0, cwph = 0;   // consumer W (slot g%3, phase g/3 parity)
    int pwsl = 2, pwph = 0;   // producer W (issues g+2)
    int cxsl = 0, cxph = 0;   // consumer X (chunk g/4)

    for (int g = 0; g < NGRP; g++) {
        if (prod) {
            if ((g & 3) == 0) {
                const int c = (g >> 2) + 1;          // one chunk ahead
                if (c < NCHUNK) ISSUE_X(c, c % 3);   // skew-safe via W-ring EMPTY bound
            }
            if (g + 2 < NGRP) {
                mbar_wait(EMPTYW(pwsl), pwph ^ 1);
                ISSUE_W(g + 2, pwsl);
                if (++pwsl == 3) { pwsl = 0; pwph ^= 1; }
            }
        }
        mbar_wait(FULLW(cwsl), cwph);
        if ((g & 3) == 0) mbar_wait(FULLX(cxsl), cxph);

        const float* wst = ws + cwsl * WS_STAGE_F + wr0 * GRP;
        const float* xb  = xr + cxsl * XR_STAGE_F + (half * 8) * CHUNK;
        float s[8];
#pragma unroll
        for (int r = 0; r < 8; r++) s[r] = sc[(wr0 + r) * NGRP + g];

        const int jb = (g & 3) * GRP;   // group offset within x chunk
#pragma unroll
        for (int k = 0; k < 4; k++) {
            const int kc  = lane + 32 * k;   // W column within group (0..127)
            const int col = jb + kc;         // x column within chunk (0..511)
            ull x2[4];
#pragma unroll
            for (int q = 0; q < 4; q++)
                x2[q] = packab(xb[(2 * q) * CHUNK + col],
                               xb[(2 * q + 1) * CHUNK + col]);
#pragma unroll
            for (int r = 0; r < 8; r++) {
                const ull w2 = pack2(wst[r * GRP + kc] * s[r]);
#pragma unroll
                for (int q = 0; q < 4; q++) fma2(acc[r][q], w2, x2[q]);
            }
        }

        if (lane == 0) mbar_arrive(EMPTYW(cwsl));    // elected, count=16 total
        if (++cwsl == 3) { cwsl = 0; cwph ^= 1; }
        if ((g & 3) == 3) { if (++cxsl == 3) { cxsl = 0; cxph ^= 1; } }
    }

    // ---- butterfly reduction across lanes
#pragma unroll
    for (int r = 0; r < 8; r++)
#pragma unroll
        for (int q = 0; q < 4; q++) {
            ull v = acc[r][q];
#pragma unroll
            for (int off = 16; off > 0; off >>= 1)
                v = add2(v, __shfl_xor_sync(0xffffffffu, v, off));
            acc[r][q] = v;
        }

    // ---- writeback: lane (r*4+q) -> row wr0+r, batches (half*8+2q, +1)
#pragma unroll
    for (int r = 0; r < 8; r++)
#pragma unroll
        for (int q = 0; q < 4; q++)
            if (lane == r * 4 + q) {
                const int row = row0 + wr0 + r;
                const int b0  = half * 8 + 2 * q;
                const float bv = __ldg(bias + row);
                float lo, hi;
                unpack2(acc[r][q], lo, hi);
                out[(size_t)b0 * OUT_F + row]       = lo + bv;
                out[(size_t)(b0 + 1) * OUT_F + row] = hi + bv;
            }
}

extern "C" void kernel_launch(void* const* d_in, const int* in_sizes, int n_in,
                              void* d_out, int out_size)
{
    const float* x     = (const float*)d_in[0]; // [16, 8192]
    const float* W     = (const float*)d_in[1]; // [8192, 8192]
    const float* scale = (const float*)d_in[2]; // [8192, 64]
    const float* bias  = (const float*)d_in[3]; // [1, 8192]
    // d_in[4] = types — constant lookup in reference; no float math: unused
    float* out = (float*)d_out;                 // [16, 8192]

    cudaFuncSetAttribute(axcore_linear_kernel,
                         cudaFuncAttributeMaxDynamicSharedMemorySize, SMEM_TOTAL);

    dim3 grid(OUT_F / RPB); // 128
    dim3 block(THREADS);    // 512
    axcore_linear_kernel<<<grid, block, SMEM_TOTAL>>>(x, W, scale, bias, out);
}